// round 4
// baseline (speedup 1.0000x reference)
#include <cuda_runtime.h>
#include <cuda_bf16.h>
#include <cstdint>

// ============================================================================
// VCLinear: out[b,e] = sum_c basis_c(t_b) * (feats @ W_c)[b,e] + bias[e]
//
// sm_103 (non-'a') target: tcgen05 unavailable -> mma.sync (HMMA) GEMM.
// bf16 hi/lo 3-term compensated GEMM, fp32 accumulate, basis applied to
// register accumulators at K-segment boundaries (exact fp32).
// Pre-kernels split A (feats) and B (W) into bf16 hi/lo device scratch once.
// ============================================================================

#define M_TOTAL   32768
#define N_TOTAL   1024
#define K_SEG     1024
#define NSEG      6
#define K_TOTAL   6144
#define LDX       1025

#define M_TILE    128
#define N_TILE    128
#define K_TILE    32
#define STAGES    4
#define THREADS   256
#define ITERS     (K_TOTAL / K_TILE)     // 192
#define SEG_ITERS (K_SEG / K_TILE)       // 32

#define STAGE_BYTES 32768                // Ah 8K | Al 8K | Bh 8K | Bl 8K
#define SMEM_TOTAL  (STAGES * STAGE_BYTES + 4096)

// -------- device scratch (static allocation is allowed) --------
__device__ __align__(16) __nv_bfloat16 g_Ah[(size_t)M_TOTAL * 1024];
__device__ __align__(16) __nv_bfloat16 g_Al[(size_t)M_TOTAL * 1024];
__device__ __align__(16) __nv_bfloat16 g_Wh[(size_t)K_TOTAL * N_TOTAL];
__device__ __align__(16) __nv_bfloat16 g_Wl[(size_t)K_TOTAL * N_TOTAL];

// -------- helpers --------
__device__ __forceinline__ uint32_t smem_u32(const void* p) {
    uint32_t a;
    asm("{ .reg .u64 t; cvta.to.shared.u64 t, %1; cvt.u32.u64 %0, t; }"
        : "=r"(a) : "l"(p));
    return a;
}

// A smem: 128 rows x 32 bf16 (64B row, 4x16B chunks). Conflict-free swizzle:
// chunk' = chunk ^ ((m&6)>>1)  -> 8 consecutive rows hit 8 distinct 16B groups.
__device__ __forceinline__ uint32_t swzA(int m, int k) {
    return (uint32_t)(m * 64 + ((((k >> 3) ^ ((m & 6) >> 1)) & 3) << 4) + (k & 7) * 2);
}
// B smem: 32 rows x 128 bf16 (256B row, 16x16B chunks). chunk' = chunk ^ (k&7).
__device__ __forceinline__ uint32_t swzB(int k, int n) {
    return (uint32_t)(k * 256 + ((((n >> 3) ^ (k & 7)) & 15) << 4) + (n & 7) * 2);
}

__device__ __forceinline__ void cp16(uint32_t dst, const void* src) {
    asm volatile("cp.async.cg.shared.global [%0], [%1], 16;"
                 :: "r"(dst), "l"(src) : "memory");
}

#define CP_COMMIT() asm volatile("cp.async.commit_group;" ::: "memory")
#define CP_WAIT(n)  asm volatile("cp.async.wait_group %0;" :: "n"(n) : "memory")

#define LDSM_X4(r0, r1, r2, r3, addr) \
    asm volatile("ldmatrix.sync.aligned.m8n8.x4.shared.b16 {%0,%1,%2,%3}, [%4];" \
                 : "=r"(r0), "=r"(r1), "=r"(r2), "=r"(r3) : "r"(addr))
#define LDSM_X4T(r0, r1, r2, r3, addr) \
    asm volatile("ldmatrix.sync.aligned.m8n8.x4.trans.shared.b16 {%0,%1,%2,%3}, [%4];" \
                 : "=r"(r0), "=r"(r1), "=r"(r2), "=r"(r3) : "r"(addr))

__device__ __forceinline__ void mma16816(float* c, const uint32_t* a, const uint32_t* b) {
    asm volatile(
        "mma.sync.aligned.m16n8k16.row.col.f32.bf16.bf16.f32 "
        "{%0,%1,%2,%3}, {%4,%5,%6,%7}, {%8,%9}, {%0,%1,%2,%3};"
        : "+f"(c[0]), "+f"(c[1]), "+f"(c[2]), "+f"(c[3])
        : "r"(a[0]), "r"(a[1]), "r"(a[2]), "r"(a[3]), "r"(b[0]), "r"(b[1]));
}

// -------- pre-kernels: fp32 -> bf16 hi/lo splits --------
__global__ void __launch_bounds__(256) split_w_kernel(const float* __restrict__ w) {
    size_t i = (size_t)blockIdx.x * blockDim.x + threadIdx.x;
    if (i < (size_t)K_TOTAL * N_TOTAL) {
        float v = w[i];
        __nv_bfloat16 h = __float2bfloat16_rn(v);
        __nv_bfloat16 l = __float2bfloat16_rn(v - __bfloat162float(h));
        g_Wh[i] = h;
        g_Wl[i] = l;
    }
}

__global__ void __launch_bounds__(256) split_a_kernel(const float* __restrict__ x) {
    size_t i = (size_t)blockIdx.x * blockDim.x + threadIdx.x;
    if (i < (size_t)M_TOTAL * 1024) {
        size_t m = i >> 10;
        size_t d = i & 1023;
        float v = x[m * LDX + d];
        __nv_bfloat16 h = __float2bfloat16_rn(v);
        __nv_bfloat16 l = __float2bfloat16_rn(v - __bfloat162float(h));
        g_Ah[i] = h;
        g_Al[i] = l;
    }
}

// -------- stage loader --------
__device__ __forceinline__ void load_stage(uint32_t sbase, int it, int m0, int n0,
                                           int tid) {
    const int d0  = (it & (SEG_ITERS - 1)) * K_TILE;  // A col base within feats
    const int kg0 = it * K_TILE;                      // global W row base
    const uint32_t sAh = sbase;
    const uint32_t sAl = sbase + 8192;
    const uint32_t sBh = sbase + 16384;
    const uint32_t sBl = sbase + 24576;
    // A: 128 rows x 4 chunks = 512 tasks per buffer
    #pragma unroll
    for (int r = 0; r < 2; ++r) {
        const int task = tid + r * 256;
        const int m = task >> 2;
        const int c = task & 3;
        const uint32_t off = swzA(m, c * 8);
        const size_t g = (size_t)(m0 + m) * 1024 + d0 + c * 8;
        cp16(sAh + off, g_Ah + g);
        cp16(sAl + off, g_Al + g);
    }
    // B: 32 rows x 16 chunks = 512 tasks per buffer
    #pragma unroll
    for (int r = 0; r < 2; ++r) {
        const int task = tid + r * 256;
        const int k = task >> 4;
        const int c = task & 15;
        const uint32_t off = swzB(k, c * 8);
        const size_t g = (size_t)(kg0 + k) * N_TOTAL + n0 + c * 8;
        cp16(sBh + off, g_Wh + g);
        cp16(sBl + off, g_Wl + g);
    }
}

// -------- main GEMM kernel --------
__global__ void __launch_bounds__(THREADS, 1)
vclinear_gemm(const float* __restrict__ x,
              const float* __restrict__ bias,
              float* __restrict__ out) {
    extern __shared__ char smem[];
    const uint32_t sb = smem_u32(smem);
    const int tid = threadIdx.x;
    const int wid = tid >> 5;
    const int lane = tid & 31;
    const int warp_m = wid & 1;   // 0..1 -> 64 rows each
    const int warp_n = wid >> 1;  // 0..3 -> 32 cols each

    const int n0 = (blockIdx.x & 7) * N_TILE;   // n fastest: co-scheduled CTAs
    const int m0 = (blockIdx.x >> 3) * M_TILE;  // share A tiles in L2

    float* basis_s = reinterpret_cast<float*>(smem + STAGES * STAGE_BYTES);
    if (tid < M_TILE) {
        const float t = x[(size_t)(m0 + tid) * LDX + 1024];
        float* bs = basis_s + tid * 6;
        bs[0] = 1.0f;
        bs[1] = t;
        bs[2] = t * t;
        float r;
        r = fmaxf(t - 0.25f, 0.0f); bs[3] = r * r;
        r = fmaxf(t - 0.50f, 0.0f); bs[4] = r * r;
        r = fmaxf(t - 0.75f, 0.0f); bs[5] = r * r;
    }

    // pipeline prologue
    #pragma unroll
    for (int s = 0; s < STAGES - 1; ++s) {
        load_stage(sb + s * STAGE_BYTES, s, m0, n0, tid);
        CP_COMMIT();
    }

    float acc[4][4][4];
    float tot[4][4][4];
    #pragma unroll
    for (int a = 0; a < 4; ++a)
        #pragma unroll
        for (int b = 0; b < 4; ++b)
            #pragma unroll
            for (int i = 0; i < 4; ++i) { acc[a][b][i] = 0.0f; tot[a][b][i] = 0.0f; }

    // lane-dependent fragment address components
    const int a_row   = warp_m * 64 + (lane & 15);
    const int a_khalf = (lane >> 4) * 8;
    const int b_krow  = (lane & 7) + (lane & 8);       // 0..15
    const int b_nhalf = (lane >> 4) * 8;

    for (int it = 0; it < ITERS; ++it) {
        CP_WAIT(STAGES - 2);
        __syncthreads();
        const uint32_t st = sb + (it & (STAGES - 1)) * STAGE_BYTES;

        #pragma unroll
        for (int ks = 0; ks < 2; ++ks) {
            const int k0 = ks * 16;
            uint32_t ah[4][4], al[4][4], bh[4][2], bl[4][2];
            #pragma unroll
            for (int mt = 0; mt < 4; ++mt) {
                const int m = a_row + mt * 16;
                const uint32_t off = swzA(m, k0 + a_khalf);
                LDSM_X4(ah[mt][0], ah[mt][1], ah[mt][2], ah[mt][3], st + off);
                LDSM_X4(al[mt][0], al[mt][1], al[mt][2], al[mt][3], st + 8192 + off);
            }
            #pragma unroll
            for (int bt = 0; bt < 2; ++bt) {
                const int n = warp_n * 32 + bt * 16 + b_nhalf;
                const int k = k0 + b_krow;
                const uint32_t off = swzB(k, n);
                LDSM_X4T(bh[2 * bt][0], bh[2 * bt][1],
                         bh[2 * bt + 1][0], bh[2 * bt + 1][1], st + 16384 + off);
                LDSM_X4T(bl[2 * bt][0], bl[2 * bt][1],
                         bl[2 * bt + 1][0], bl[2 * bt + 1][1], st + 24576 + off);
            }
            #pragma unroll
            for (int mt = 0; mt < 4; ++mt) {
                #pragma unroll
                for (int nt = 0; nt < 4; ++nt) {
                    mma16816(acc[mt][nt], ah[mt], bh[nt]);  // hi*hi
                    mma16816(acc[mt][nt], ah[mt], bl[nt]);  // hi*lo
                    mma16816(acc[mt][nt], al[mt], bh[nt]);  // lo*hi
                }
            }
        }
        __syncthreads();

        if (it + STAGES - 1 < ITERS) {
            load_stage(sb + ((it + STAGES - 1) & (STAGES - 1)) * STAGE_BYTES,
                       it + STAGES - 1, m0, n0, tid);
        }
        CP_COMMIT();

        // segment boundary: fold basis_c * acc into tot (exact fp32)
        if ((it & (SEG_ITERS - 1)) == SEG_ITERS - 1) {
            const int c = it / SEG_ITERS;
            #pragma unroll
            for (int mt = 0; mt < 4; ++mt) {
                #pragma unroll
                for (int half = 0; half < 2; ++half) {
                    const int rl = warp_m * 64 + mt * 16 + (lane >> 2) + half * 8;
                    const float beta = basis_s[rl * 6 + c];
                    #pragma unroll
                    for (int nt = 0; nt < 4; ++nt) {
                        tot[mt][nt][half * 2 + 0] += beta * acc[mt][nt][half * 2 + 0];
                        tot[mt][nt][half * 2 + 1] += beta * acc[mt][nt][half * 2 + 1];
                        acc[mt][nt][half * 2 + 0] = 0.0f;
                        acc[mt][nt][half * 2 + 1] = 0.0f;
                    }
                }
            }
        }
    }

    // epilogue: tot + bias -> out
    #pragma unroll
    for (int mt = 0; mt < 4; ++mt) {
        #pragma unroll
        for (int half = 0; half < 2; ++half) {
            const int row = m0 + warp_m * 64 + mt * 16 + (lane >> 2) + half * 8;
            float* orow = out + (size_t)row * N_TOTAL;
            #pragma unroll
            for (int nt = 0; nt < 4; ++nt) {
                const int col = (blockIdx.x & 7) * N_TILE + warp_n * 32 + nt * 8 + (lane & 3) * 2;
                float2 v;
                v.x = tot[mt][nt][half * 2 + 0] + __ldg(bias + col);
                v.y = tot[mt][nt][half * 2 + 1] + __ldg(bias + col + 1);
                *reinterpret_cast<float2*>(orow + col) = v;
            }
        }
    }
}

// -------- launch --------
extern "C" void kernel_launch(void* const* d_in, const int* in_sizes, int n_in,
                              void* d_out, int out_size) {
    const float* x    = (const float*)d_in[0];   // (32768, 1025)
    const float* w    = (const float*)d_in[1];   // (6,1024,1024) == (6144,1024)
    const float* bias = (const float*)d_in[2];   // (1024,)
    float* out = (float*)d_out;                  // (32768, 1024)

    split_w_kernel<<<(K_TOTAL * N_TOTAL + 255) / 256, 256>>>(w);
    split_a_kernel<<<(M_TOTAL * 1024 + 255) / 256, 256>>>(x);

    static bool attr_set = false;
    if (!attr_set) {
        cudaFuncSetAttribute(vclinear_gemm,
                             cudaFuncAttributeMaxDynamicSharedMemorySize, SMEM_TOTAL);
        attr_set = true;
    }
    dim3 grid((M_TOTAL / M_TILE) * (N_TOTAL / N_TILE));  // 2048
    vclinear_gemm<<<grid, THREADS, SMEM_TOTAL>>>(x, bias, out);
}

// round 7
// speedup vs baseline: 2.6534x; 2.6534x over previous
#include <cuda_runtime.h>
#include <cuda_fp16.h>
#include <cstdint>

// ============================================================================
// VCLinear: out[b,e] = sum_c basis_c(t_b) * (feats @ W_c)[b,e] + bias[e]
//
// sm_103 (non-'a') target: mma.sync (HMMA) GEMM.
// SINGLE fp16 GEMM (fp32 accumulate). fp16 u=2^-11 -> norm rel_err ~4e-4
// < 1e-3 gate. Basis applied in fp32 to register accumulators at K-segment
// boundaries (exact).
// R5 fix: split_a_kernel used LDG.128 on rows with stride 1025 floats
// (row base % 16B == 4) -> misaligned-address trap. Now scalar loads.
// ============================================================================

#define M_TOTAL   32768
#define N_TOTAL   1024
#define K_SEG     1024
#define K_TOTAL   6144
#define LDX       1025

#define M_TILE    128
#define N_TILE    128
#define K_TILE    64
#define STAGES    4
#define THREADS   256
#define ITERS     (K_TOTAL / K_TILE)     // 96
#define SEG_ITERS (K_SEG / K_TILE)       // 16

#define STAGE_BYTES 32768                // A 16K | B 16K
#define SMEM_TOTAL  (STAGES * STAGE_BYTES + 4096)

// -------- device scratch (static allocation allowed) --------
__device__ __align__(16) __half g_A[(size_t)M_TOTAL * 1024];
__device__ __align__(16) __half g_W[(size_t)K_TOTAL * N_TOTAL];

// -------- helpers --------
__device__ __forceinline__ uint32_t smem_u32(const void* p) {
    uint32_t a;
    asm("{ .reg .u64 t; cvta.to.shared.u64 t, %1; cvt.u32.u64 %0, t; }"
        : "=r"(a) : "l"(p));
    return a;
}

// A smem: 128 rows x 64 fp16 = 128B/row, 8x16B chunks, SW128-style swizzle:
// chunk' = chunk ^ (row&7) -> 8 consecutive rows hit distinct bank groups.
__device__ __forceinline__ uint32_t swzA(int m, int k) {
    return (uint32_t)(m * 128 + ((((k >> 3) ^ (m & 7)) & 7) << 4) + (k & 7) * 2);
}
// B smem: 64 k-rows x 128 n-cols = 256B/row, 16x16B chunks: chunk' = chunk ^ (k&7).
__device__ __forceinline__ uint32_t swzB(int k, int n) {
    return (uint32_t)(k * 256 + ((((n >> 3) ^ (k & 7)) & 15) << 4) + (n & 7) * 2);
}

__device__ __forceinline__ void cp16(uint32_t dst, const void* src) {
    asm volatile("cp.async.cg.shared.global [%0], [%1], 16;"
                 :: "r"(dst), "l"(src) : "memory");
}

#define CP_COMMIT() asm volatile("cp.async.commit_group;" ::: "memory")
#define CP_WAIT(n)  asm volatile("cp.async.wait_group %0;" :: "n"(n) : "memory")

#define LDSM_X4(r0, r1, r2, r3, addr) \
    asm volatile("ldmatrix.sync.aligned.m8n8.x4.shared.b16 {%0,%1,%2,%3}, [%4];" \
                 : "=r"(r0), "=r"(r1), "=r"(r2), "=r"(r3) : "r"(addr))
#define LDSM_X4T(r0, r1, r2, r3, addr) \
    asm volatile("ldmatrix.sync.aligned.m8n8.x4.trans.shared.b16 {%0,%1,%2,%3}, [%4];" \
                 : "=r"(r0), "=r"(r1), "=r"(r2), "=r"(r3) : "r"(addr))

__device__ __forceinline__ void mma16816(float* c, const uint32_t* a, const uint32_t* b) {
    asm volatile(
        "mma.sync.aligned.m16n8k16.row.col.f32.f16.f16.f32 "
        "{%0,%1,%2,%3}, {%4,%5,%6,%7}, {%8,%9}, {%0,%1,%2,%3};"
        : "+f"(c[0]), "+f"(c[1]), "+f"(c[2]), "+f"(c[3])
        : "r"(a[0]), "r"(a[1]), "r"(a[2]), "r"(a[3]), "r"(b[0]), "r"(b[1]));
}

// -------- pre-kernels: fp32 -> fp16 --------
__global__ void __launch_bounds__(256) split_w_kernel(const float* __restrict__ w) {
    size_t i = ((size_t)blockIdx.x * blockDim.x + threadIdx.x) * 4;
    if (i < (size_t)K_TOTAL * N_TOTAL) {
        const float4 v = *reinterpret_cast<const float4*>(w + i);
        *reinterpret_cast<__half2*>(g_W + i)     = __floats2half2_rn(v.x, v.y);
        *reinterpret_cast<__half2*>(g_W + i + 2) = __floats2half2_rn(v.z, v.w);
    }
}

__global__ void __launch_bounds__(256) split_a_kernel(const float* __restrict__ x) {
    size_t i = ((size_t)blockIdx.x * blockDim.x + threadIdx.x) * 4;
    if (i < (size_t)M_TOTAL * 1024) {
        const size_t m = i >> 10;
        const size_t d = i & 1023;
        // x rows have stride 1025 floats: row base % 16B == 4*(m%4) -> NO LDG.128.
        const float* p = x + m * LDX + d;
        const float v0 = p[0];
        const float v1 = p[1];
        const float v2 = p[2];
        const float v3 = p[3];
        *reinterpret_cast<__half2*>(g_A + i)     = __floats2half2_rn(v0, v1);
        *reinterpret_cast<__half2*>(g_A + i + 2) = __floats2half2_rn(v2, v3);
    }
}

// -------- stage loader: A 128x64 fp16 + B 64x128 fp16 --------
__device__ __forceinline__ void load_stage(uint32_t sbase, int it, int m0, int n0,
                                           int tid) {
    const int d0  = (it & (SEG_ITERS - 1)) * K_TILE;  // A col base within feats
    const int kg0 = it * K_TILE;                      // global W row base
    const uint32_t sA = sbase;
    const uint32_t sB = sbase + 16384;
    // A: 128 rows x 8 chunks = 1024 tasks
    #pragma unroll
    for (int r = 0; r < 4; ++r) {
        const int task = tid + r * 256;
        const int m = task >> 3;
        const int c = task & 7;
        cp16(sA + swzA(m, c * 8), g_A + (size_t)(m0 + m) * 1024 + d0 + c * 8);
    }
    // B: 64 rows x 16 chunks = 1024 tasks
    #pragma unroll
    for (int r = 0; r < 4; ++r) {
        const int task = tid + r * 256;
        const int k = task >> 4;
        const int c = task & 15;
        cp16(sB + swzB(k, c * 8), g_W + (size_t)(kg0 + k) * N_TOTAL + n0 + c * 8);
    }
}

// -------- main GEMM kernel --------
__global__ void __launch_bounds__(THREADS, 1)
vclinear_gemm(const float* __restrict__ x,
              const float* __restrict__ bias,
              float* __restrict__ out) {
    extern __shared__ char smem[];
    const uint32_t sb = smem_u32(smem);
    const int tid = threadIdx.x;
    const int wid = tid >> 5;
    const int lane = tid & 31;
    const int warp_m = wid & 1;   // 0..1 -> 64 rows each
    const int warp_n = wid >> 1;  // 0..3 -> 32 cols each

    const int n0 = (blockIdx.x & 7) * N_TILE;   // n fastest: co-scheduled CTAs
    const int m0 = (blockIdx.x >> 3) * M_TILE;  // share A tiles in L2

    float* basis_s = reinterpret_cast<float*>(smem + STAGES * STAGE_BYTES);
    if (tid < M_TILE) {
        const float t = x[(size_t)(m0 + tid) * LDX + 1024];
        float* bs = basis_s + tid * 6;
        bs[0] = 1.0f;
        bs[1] = t;
        bs[2] = t * t;
        float r;
        r = fmaxf(t - 0.25f, 0.0f); bs[3] = r * r;
        r = fmaxf(t - 0.50f, 0.0f); bs[4] = r * r;
        r = fmaxf(t - 0.75f, 0.0f); bs[5] = r * r;
    }

    // pipeline prologue
    #pragma unroll
    for (int s = 0; s < STAGES - 1; ++s) {
        load_stage(sb + s * STAGE_BYTES, s, m0, n0, tid);
        CP_COMMIT();
    }

    float acc[4][4][4];
    float tot[4][4][4];
    #pragma unroll
    for (int a = 0; a < 4; ++a)
        #pragma unroll
        for (int b = 0; b < 4; ++b)
            #pragma unroll
            for (int i = 0; i < 4; ++i) { acc[a][b][i] = 0.0f; tot[a][b][i] = 0.0f; }

    // lane-dependent fragment address components
    const int a_row   = warp_m * 64 + (lane & 15);
    const int a_khalf = (lane >> 4) * 8;
    const int b_krow  = (lane & 7) + (lane & 8);       // 0..15
    const int b_nhalf = (lane >> 4) * 8;

    for (int it = 0; it < ITERS; ++it) {
        CP_WAIT(STAGES - 2);
        __syncthreads();
        const uint32_t st  = sb + (it & (STAGES - 1)) * STAGE_BYTES;
        const uint32_t stB = st + 16384;

        #pragma unroll
        for (int ks = 0; ks < 4; ++ks) {
            const int k0 = ks * 16;
            uint32_t ah[4][4], bh[4][2];
            #pragma unroll
            for (int mt = 0; mt < 4; ++mt) {
                const uint32_t off = swzA(a_row + mt * 16, k0 + a_khalf);
                LDSM_X4(ah[mt][0], ah[mt][1], ah[mt][2], ah[mt][3], st + off);
            }
            #pragma unroll
            for (int bt = 0; bt < 2; ++bt) {
                const int n = warp_n * 32 + bt * 16 + b_nhalf;
                const uint32_t off = swzB(k0 + b_krow, n);
                LDSM_X4T(bh[2 * bt][0], bh[2 * bt][1],
                         bh[2 * bt + 1][0], bh[2 * bt + 1][1], stB + off);
            }
            #pragma unroll
            for (int mt = 0; mt < 4; ++mt) {
                #pragma unroll
                for (int nt = 0; nt < 4; ++nt) {
                    mma16816(acc[mt][nt], ah[mt], bh[nt]);
                }
            }
        }
        __syncthreads();

        if (it + STAGES - 1 < ITERS) {
            load_stage(sb + ((it + STAGES - 1) & (STAGES - 1)) * STAGE_BYTES,
                       it + STAGES - 1, m0, n0, tid);
        }
        CP_COMMIT();

        // segment boundary: fold basis_c * acc into tot (exact fp32)
        if ((it & (SEG_ITERS - 1)) == SEG_ITERS - 1) {
            const int c = it / SEG_ITERS;
            #pragma unroll
            for (int mt = 0; mt < 4; ++mt) {
                #pragma unroll
                for (int half = 0; half < 2; ++half) {
                    const int rl = warp_m * 64 + mt * 16 + (lane >> 2) + half * 8;
                    const float beta = basis_s[rl * 6 + c];
                    #pragma unroll
                    for (int nt = 0; nt < 4; ++nt) {
                        tot[mt][nt][half * 2 + 0] += beta * acc[mt][nt][half * 2 + 0];
                        tot[mt][nt][half * 2 + 1] += beta * acc[mt][nt][half * 2 + 1];
                        acc[mt][nt][half * 2 + 0] = 0.0f;
                        acc[mt][nt][half * 2 + 1] = 0.0f;
                    }
                }
            }
        }
    }

    // epilogue: tot + bias -> out
    #pragma unroll
    for (int mt = 0; mt < 4; ++mt) {
        #pragma unroll
        for (int half = 0; half < 2; ++half) {
            const int row = m0 + warp_m * 64 + mt * 16 + (lane >> 2) + half * 8;
            float* orow = out + (size_t)row * N_TOTAL;
            #pragma unroll
            for (int nt = 0; nt < 4; ++nt) {
                const int col = n0 + warp_n * 32 + nt * 8 + (lane & 3) * 2;
                float2 v;
                v.x = tot[mt][nt][half * 2 + 0] + __ldg(bias + col);
                v.y = tot[mt][nt][half * 2 + 1] + __ldg(bias + col + 1);
                *reinterpret_cast<float2*>(orow + col) = v;
            }
        }
    }
}

// -------- launch --------
extern "C" void kernel_launch(void* const* d_in, const int* in_sizes, int n_in,
                              void* d_out, int out_size) {
    const float* x    = (const float*)d_in[0];   // (32768, 1025)
    const float* w    = (const float*)d_in[1];   // (6,1024,1024) == (6144,1024)
    const float* bias = (const float*)d_in[2];   // (1024,)
    float* out = (float*)d_out;                  // (32768, 1024)

    split_w_kernel<<<(K_TOTAL * N_TOTAL / 4 + 255) / 256, 256>>>(w);
    split_a_kernel<<<(M_TOTAL * 1024 / 4 + 255) / 256, 256>>>(x);

    static bool attr_set = false;
    if (!attr_set) {
        cudaFuncSetAttribute(vclinear_gemm,
                             cudaFuncAttributeMaxDynamicSharedMemorySize, SMEM_TOTAL);
        attr_set = true;
    }
    dim3 grid((M_TOTAL / M_TILE) * (N_TOTAL / N_TILE));  // 2048
    vclinear_gemm<<<grid, THREADS, SMEM_TOTAL>>>(x, bias, out);
}

// round 8
// speedup vs baseline: 3.8824x; 1.4632x over previous
#include <cuda_runtime.h>
#include <cuda_fp16.h>
#include <cstdint>

// ============================================================================
// VCLinear: out[b,e] = sum_c basis_c(t_b) * (feats @ W_c)[b,e] + bias[e]
//
// Spline identity: on each knot interval I (4 of them), the basis combination
// is quadratic in t:  out[b] = sum_{p=0..2} t_b^p * (feats[b] @ P_p^I) + bias,
//   P0^I = W0 + sum_{active j} kj^2 W_{3+j}
//   P1^I = W1 - sum_{active j} 2 kj W_{3+j}
//   P2^I = W2 + sum_{active j}        W_{3+j}
// -> rows bucketed by interval, single fp16 HMMA GEMM with K=3072 (vs 6144),
//    t^p applied to A fragments in-register (HMUL2), p=0 segment exact.
// 2x less tensor work than round-7 (which was HMMA-pipe bound at ~413 TF/s).
// ============================================================================

#define M_TOTAL   32768
#define N_TOTAL   1024
#define K_RED     3072
#define LDX       1025
#define PAD_M     33280              // 32768 + 4*128 slack
#define MAX_TILES 260                // PAD_M / 128

#define M_TILE    128
#define N_TILE    128
#define K_TILE    64
#define STAGES    4
#define THREADS   256
#define ITERS     (K_RED / K_TILE)   // 48
#define SEG_ITERS 16                 // 1024 / 64

#define STAGE_BYTES 32768            // A 16K | B 16K
#define SM_PERM     (STAGES * STAGE_BYTES)          // 128 ints = 512B
#define SM_T        (SM_PERM + 512)                 // 128 floats = 512B
#define SMEM_TOTAL  (SM_T + 512)

// -------- device scratch --------
__device__ __align__(16) __half g_A[(size_t)M_TOTAL * 1024];
__device__ __align__(16) __half g_P[(size_t)4 * K_RED * N_TOTAL];  // 25 MB
__device__ int   g_perm[PAD_M];
__device__ float g_tp[PAD_M];
__device__ int   g_tile_int[MAX_TILES];

// -------- helpers --------
__device__ __forceinline__ uint32_t smem_u32(const void* p) {
    uint32_t a;
    asm("{ .reg .u64 t; cvta.to.shared.u64 t, %1; cvt.u32.u64 %0, t; }"
        : "=r"(a) : "l"(p));
    return a;
}

__device__ __forceinline__ uint32_t swzA(int m, int k) {
    return (uint32_t)(m * 128 + ((((k >> 3) ^ (m & 7)) & 7) << 4) + (k & 7) * 2);
}
__device__ __forceinline__ uint32_t swzB(int k, int n) {
    return (uint32_t)(k * 256 + ((((n >> 3) ^ (k & 7)) & 15) << 4) + (n & 7) * 2);
}

__device__ __forceinline__ void cp16(uint32_t dst, const void* src) {
    asm volatile("cp.async.cg.shared.global [%0], [%1], 16;"
                 :: "r"(dst), "l"(src) : "memory");
}

#define CP_COMMIT() asm volatile("cp.async.commit_group;" ::: "memory")
#define CP_WAIT(n)  asm volatile("cp.async.wait_group %0;" :: "n"(n) : "memory")

#define LDSM_X4(r0, r1, r2, r3, addr) \
    asm volatile("ldmatrix.sync.aligned.m8n8.x4.shared.b16 {%0,%1,%2,%3}, [%4];" \
                 : "=r"(r0), "=r"(r1), "=r"(r2), "=r"(r3) : "r"(addr))
#define LDSM_X4T(r0, r1, r2, r3, addr) \
    asm volatile("ldmatrix.sync.aligned.m8n8.x4.trans.shared.b16 {%0,%1,%2,%3}, [%4];" \
                 : "=r"(r0), "=r"(r1), "=r"(r2), "=r"(r3) : "r"(addr))

__device__ __forceinline__ void mma16816(float* c, const uint32_t* a, const uint32_t* b) {
    asm volatile(
        "mma.sync.aligned.m16n8k16.row.col.f32.f16.f16.f32 "
        "{%0,%1,%2,%3}, {%4,%5,%6,%7}, {%8,%9}, {%0,%1,%2,%3};"
        : "+f"(c[0]), "+f"(c[1]), "+f"(c[2]), "+f"(c[3])
        : "r"(a[0]), "r"(a[1]), "r"(a[2]), "r"(a[3]), "r"(b[0]), "r"(b[1]));
}

__device__ __forceinline__ uint32_t hmul2u(uint32_t a, uint32_t b) {
    __half2 r = __hmul2(*reinterpret_cast<__half2*>(&a),
                        *reinterpret_cast<__half2*>(&b));
    return *reinterpret_cast<uint32_t*>(&r);
}

// -------- pre-kernel: feats fp32 -> fp16 --------
__global__ void __launch_bounds__(256) split_a_kernel(const float* __restrict__ x) {
    size_t i = ((size_t)blockIdx.x * blockDim.x + threadIdx.x) * 4;
    if (i < (size_t)M_TOTAL * 1024) {
        const size_t m = i >> 10;
        const size_t d = i & 1023;
        const float* p = x + m * LDX + d;   // stride 1025: no LDG.128 allowed
        *reinterpret_cast<__half2*>(g_A + i)     = __floats2half2_rn(p[0], p[1]);
        *reinterpret_cast<__half2*>(g_A + i + 2) = __floats2half2_rn(p[2], p[3]);
    }
}

// -------- pre-kernel: build P matrices (4 intervals x 3 powers) --------
__global__ void __launch_bounds__(256) build_p_kernel(const float* __restrict__ w) {
    const size_t idx = (size_t)blockIdx.x * 256 + threadIdx.x;  // d*1024+e
    if (idx >= (size_t)1 << 20) return;
    const float w0 = w[idx];
    const float w1 = w[(size_t)1 * 1048576 + idx];
    const float w2 = w[(size_t)2 * 1048576 + idx];
    const float w3 = w[(size_t)3 * 1048576 + idx];
    const float w4 = w[(size_t)4 * 1048576 + idx];
    const float w5 = w[(size_t)5 * 1048576 + idx];
    float p0 = w0, p1 = w1, p2 = w2;
    #pragma unroll
    for (int i = 0; i < 4; ++i) {
        const size_t base = (size_t)i * 3 * 1048576 + idx;
        g_P[base]               = __float2half_rn(p0);
        g_P[base + 1048576]     = __float2half_rn(p1);
        g_P[base + 2 * 1048576] = __float2half_rn(p2);
        // accumulate next knot (0.25, 0.5, 0.75)
        if (i == 0) { p0 += 0.0625f * w3; p1 -= 0.5f * w3; p2 += w3; }
        if (i == 1) { p0 += 0.25f   * w4; p1 -= 1.0f * w4; p2 += w4; }
        if (i == 2) { p0 += 0.5625f * w5; p1 -= 1.5f * w5; p2 += w5; }
    }
}

// -------- bucket kernel: partition rows by knot interval (1 CTA) --------
__global__ void __launch_bounds__(1024) bucket_kernel(const float* __restrict__ x) {
    __shared__ int s_cnt[4], s_cur[4];
    const int tid = threadIdx.x;
    if (tid < 4) s_cnt[tid] = 0;
    for (int i = tid; i < PAD_M; i += 1024) g_perm[i] = -1;
    for (int i = tid; i < MAX_TILES; i += 1024) g_tile_int[i] = -1;
    __syncthreads();

    // pass 1: per-thread counts over a contiguous 32-row chunk
    const int base = tid * 32;
    int c[4] = {0, 0, 0, 0};
    for (int r = 0; r < 32; ++r) {
        const float t = x[(size_t)(base + r) * LDX + 1024];
        const int iv = (t > 0.25f) + (t > 0.5f) + (t > 0.75f);
        c[iv]++;
    }
    #pragma unroll
    for (int i = 0; i < 4; ++i) atomicAdd(&s_cnt[i], c[i]);
    __syncthreads();

    if (tid == 0) {
        int s = 0;
        #pragma unroll
        for (int i = 0; i < 4; ++i) {
            const int nt = (s_cnt[i] + 127) >> 7;
            const int ts = s >> 7;
            for (int j = 0; j < nt; ++j) g_tile_int[ts + j] = i;
            s_cur[i] = s;
            s += nt * 128;
        }
    }
    __syncthreads();

    // reserve contiguous ranges, then write without atomics
    int my[4];
    #pragma unroll
    for (int i = 0; i < 4; ++i) my[i] = atomicAdd(&s_cur[i], c[i]);
    for (int r = 0; r < 32; ++r) {
        const float t = x[(size_t)(base + r) * LDX + 1024];
        const int iv = (t > 0.25f) + (t > 0.5f) + (t > 0.75f);
        const int pos = my[iv]++;
        g_perm[pos] = base + r;
        g_tp[pos] = t;
    }
}

// -------- stage loader --------
__device__ __forceinline__ void load_stage(uint32_t sbase, int it,
                                           const int* __restrict__ perm_s,
                                           const __half* __restrict__ Pbase,
                                           int n0, int tid) {
    const int d0  = (it & (SEG_ITERS - 1)) * K_TILE;  // col base within feats
    const int kg0 = it * K_TILE;                      // row base within K_RED
    const uint32_t sA = sbase;
    const uint32_t sB = sbase + 16384;
    // A: 128 rows x 8 chunks (gathered rows)
    #pragma unroll
    for (int r = 0; r < 4; ++r) {
        const int task = tid + r * 256;
        const int m = task >> 3;
        const int c = task & 7;
        const int rg = perm_s[m] < 0 ? 0 : perm_s[m];
        cp16(sA + swzA(m, c * 8), g_A + (size_t)rg * 1024 + d0 + c * 8);
    }
    // B: 64 rows x 16 chunks
    #pragma unroll
    for (int r = 0; r < 4; ++r) {
        const int task = tid + r * 256;
        const int k = task >> 4;
        const int c = task & 15;
        cp16(sB + swzB(k, c * 8), Pbase + (size_t)(kg0 + k) * N_TOTAL + n0 + c * 8);
    }
}

// -------- main GEMM kernel --------
__global__ void __launch_bounds__(THREADS, 1)
vclinear_gemm(const float* __restrict__ bias,
              float* __restrict__ out) {
    const int mt = blockIdx.x >> 3;
    const int interval = g_tile_int[mt];
    if (interval < 0) return;
    const int nt = blockIdx.x & 7;
    const int n0 = nt * N_TILE;

    extern __shared__ char smem[];
    const uint32_t sb = smem_u32(smem);
    const int tid = threadIdx.x;
    const int wid = tid >> 5;
    const int lane = tid & 31;
    const int warp_m = wid & 1;
    const int warp_n = wid >> 1;

    int* perm_s = reinterpret_cast<int*>(smem + SM_PERM);
    float* t_s  = reinterpret_cast<float*>(smem + SM_T);
    if (tid < M_TILE) {
        perm_s[tid] = g_perm[mt * M_TILE + tid];
        t_s[tid]    = g_tp[mt * M_TILE + tid];
    }
    __syncthreads();

    const __half* Pbase = g_P + (size_t)interval * K_RED * N_TOTAL;

    // pipeline prologue
    #pragma unroll
    for (int s = 0; s < STAGES - 1; ++s) {
        load_stage(sb + s * STAGE_BYTES, s, perm_s, Pbase, n0, tid);
        CP_COMMIT();
    }

    float acc[4][4][4];
    #pragma unroll
    for (int a = 0; a < 4; ++a)
        #pragma unroll
        for (int b = 0; b < 4; ++b)
            #pragma unroll
            for (int i = 0; i < 4; ++i) acc[a][b][i] = 0.0f;

    const int a_row   = warp_m * 64 + (lane & 15);
    const int a_khalf = (lane >> 4) * 8;
    const int b_krow  = (lane & 7) + (lane & 8);
    const int b_nhalf = (lane >> 4) * 8;

    // per-mt row t values (rows r and r+8 of each 16-row fragment block)
    float tA0[4], tA1[4];
    #pragma unroll
    for (int mtf = 0; mtf < 4; ++mtf) {
        const int r0 = warp_m * 64 + mtf * 16 + (lane >> 2);
        tA0[mtf] = t_s[r0];
        tA1[mtf] = t_s[r0 + 8];
    }
    uint32_t bA0[4], bA1[4];   // half2 t^p broadcast, valid when p >= 1

    for (int it = 0; it < ITERS; ++it) {
        if (it == SEG_ITERS) {          // p = 1: scale by t
            #pragma unroll
            for (int m = 0; m < 4; ++m) {
                __half2 h0 = __float2half2_rn(tA0[m]);
                __half2 h1 = __float2half2_rn(tA1[m]);
                bA0[m] = *reinterpret_cast<uint32_t*>(&h0);
                bA1[m] = *reinterpret_cast<uint32_t*>(&h1);
            }
        } else if (it == 2 * SEG_ITERS) {  // p = 2: scale by t^2
            #pragma unroll
            for (int m = 0; m < 4; ++m) {
                __half2 h0 = __float2half2_rn(tA0[m] * tA0[m]);
                __half2 h1 = __float2half2_rn(tA1[m] * tA1[m]);
                bA0[m] = *reinterpret_cast<uint32_t*>(&h0);
                bA1[m] = *reinterpret_cast<uint32_t*>(&h1);
            }
        }
        const bool scale = it >= SEG_ITERS;

        CP_WAIT(STAGES - 2);
        __syncthreads();
        const uint32_t st  = sb + (it & (STAGES - 1)) * STAGE_BYTES;
        const uint32_t stB = st + 16384;

        #pragma unroll
        for (int ks = 0; ks < 4; ++ks) {
            const int k0 = ks * 16;
            uint32_t ah[4][4], bh[4][2];
            #pragma unroll
            for (int m = 0; m < 4; ++m) {
                const uint32_t off = swzA(a_row + m * 16, k0 + a_khalf);
                LDSM_X4(ah[m][0], ah[m][1], ah[m][2], ah[m][3], st + off);
                if (scale) {
                    ah[m][0] = hmul2u(ah[m][0], bA0[m]);
                    ah[m][1] = hmul2u(ah[m][1], bA1[m]);
                    ah[m][2] = hmul2u(ah[m][2], bA0[m]);
                    ah[m][3] = hmul2u(ah[m][3], bA1[m]);
                }
            }
            #pragma unroll
            for (int bt = 0; bt < 2; ++bt) {
                const int n = warp_n * 32 + bt * 16 + b_nhalf;
                const uint32_t off = swzB(k0 + b_krow, n);
                LDSM_X4T(bh[2 * bt][0], bh[2 * bt][1],
                         bh[2 * bt + 1][0], bh[2 * bt + 1][1], stB + off);
            }
            #pragma unroll
            for (int m = 0; m < 4; ++m)
                #pragma unroll
                for (int n = 0; n < 4; ++n)
                    mma16816(acc[m][n], ah[m], bh[n]);
        }
        __syncthreads();

        if (it + STAGES - 1 < ITERS) {
            load_stage(sb + ((it + STAGES - 1) & (STAGES - 1)) * STAGE_BYTES,
                       it + STAGES - 1, perm_s, Pbase, n0, tid);
        }
        CP_COMMIT();
    }

    // epilogue: scatter rows via perm, add bias, skip invalid
    #pragma unroll
    for (int m = 0; m < 4; ++m) {
        #pragma unroll
        for (int half = 0; half < 2; ++half) {
            const int rl = warp_m * 64 + m * 16 + (lane >> 2) + half * 8;
            const int rg = perm_s[rl];
            if (rg < 0) continue;
            float* orow = out + (size_t)rg * N_TOTAL;
            #pragma unroll
            for (int n = 0; n < 4; ++n) {
                const int col = n0 + warp_n * 32 + n * 8 + (lane & 3) * 2;
                float2 v;
                v.x = acc[m][n][half * 2 + 0] + __ldg(bias + col);
                v.y = acc[m][n][half * 2 + 1] + __ldg(bias + col + 1);
                *reinterpret_cast<float2*>(orow + col) = v;
            }
        }
    }
}

// -------- launch --------
extern "C" void kernel_launch(void* const* d_in, const int* in_sizes, int n_in,
                              void* d_out, int out_size) {
    const float* x    = (const float*)d_in[0];   // (32768, 1025)
    const float* w    = (const float*)d_in[1];   // (6,1024,1024)
    const float* bias = (const float*)d_in[2];   // (1024,)
    float* out = (float*)d_out;                  // (32768, 1024)

    split_a_kernel<<<(M_TOTAL * 1024 / 4 + 255) / 256, 256>>>(x);
    bucket_kernel<<<1, 1024>>>(x);
    build_p_kernel<<<(1 << 20) / 256, 256>>>(w);

    static bool attr_set = false;
    if (!attr_set) {
        cudaFuncSetAttribute(vclinear_gemm,
                             cudaFuncAttributeMaxDynamicSharedMemorySize, SMEM_TOTAL);
        attr_set = true;
    }
    vclinear_gemm<<<MAX_TILES * 8, THREADS, SMEM_TOTAL>>>(bias, out);
}

// round 10
// speedup vs baseline: 4.8632x; 1.2526x over previous
#include <cuda_runtime.h>
#include <cuda_fp16.h>
#include <cstdint>

// ============================================================================
// VCLinear: out[b,e] = sum_c basis_c(t_b) * (feats @ W_c)[b,e] + bias[e]
//
// Spline identity: per knot interval I, basis combo is quadratic in t:
//   out[b] = sum_{p=0..2} t_b^p * (feats[b] @ P_p^I) + bias
// Rows bucketed by interval, single fp16 HMMA GEMM K=3072, t^p applied to A
// fragments in-register.
// R9: occupancy fix (R8: 1 CTA/SM, tensor=49%). STAGES 4->3 (97KB smem),
// launch_bounds(256,2) -> 2 CTAs/SM; single __syncthreads per mainloop iter;
// bucket kernel single-pass via smem t-cache.
// ============================================================================

#define M_TOTAL   32768
#define N_TOTAL   1024
#define K_RED     3072
#define LDX       1025
#define PAD_M     33280              // 32768 + 4*128 slack
#define MAX_TILES 260

#define M_TILE    128
#define N_TILE    128
#define K_TILE    64
#define STAGES    3
#define THREADS   256
#define ITERS     (K_RED / K_TILE)   // 48
#define SEG_ITERS 16                 // 1024 / 64

#define STAGE_BYTES 32768            // A 16K | B 16K
#define SM_PERM     (STAGES * STAGE_BYTES)          // 128 ints
#define SM_T        (SM_PERM + 512)                 // 128 floats
#define SMEM_TOTAL  (SM_T + 512)                    // 99328 B

// -------- device scratch --------
__device__ __align__(16) __half g_A[(size_t)M_TOTAL * 1024];
__device__ __align__(16) __half g_P[(size_t)4 * K_RED * N_TOTAL];  // 25 MB
__device__ int   g_perm[PAD_M];
__device__ float g_tp[PAD_M];
__device__ int   g_tile_int[MAX_TILES];

// -------- helpers --------
__device__ __forceinline__ uint32_t smem_u32(const void* p) {
    uint32_t a;
    asm("{ .reg .u64 t; cvta.to.shared.u64 t, %1; cvt.u32.u64 %0, t; }"
        : "=r"(a) : "l"(p));
    return a;
}

__device__ __forceinline__ uint32_t swzA(int m, int k) {
    return (uint32_t)(m * 128 + ((((k >> 3) ^ (m & 7)) & 7) << 4) + (k & 7) * 2);
}
__device__ __forceinline__ uint32_t swzB(int k, int n) {
    return (uint32_t)(k * 256 + ((((n >> 3) ^ (k & 7)) & 15) << 4) + (n & 7) * 2);
}

__device__ __forceinline__ void cp16(uint32_t dst, const void* src) {
    asm volatile("cp.async.cg.shared.global [%0], [%1], 16;"
                 :: "r"(dst), "l"(src) : "memory");
}

#define CP_COMMIT() asm volatile("cp.async.commit_group;" ::: "memory")
#define CP_WAIT(n)  asm volatile("cp.async.wait_group %0;" :: "n"(n) : "memory")

#define LDSM_X4(r0, r1, r2, r3, addr) \
    asm volatile("ldmatrix.sync.aligned.m8n8.x4.shared.b16 {%0,%1,%2,%3}, [%4];" \
                 : "=r"(r0), "=r"(r1), "=r"(r2), "=r"(r3) : "r"(addr))
#define LDSM_X4T(r0, r1, r2, r3, addr) \
    asm volatile("ldmatrix.sync.aligned.m8n8.x4.trans.shared.b16 {%0,%1,%2,%3}, [%4];" \
                 : "=r"(r0), "=r"(r1), "=r"(r2), "=r"(r3) : "r"(addr))

__device__ __forceinline__ void mma16816(float* c, const uint32_t* a, const uint32_t* b) {
    asm volatile(
        "mma.sync.aligned.m16n8k16.row.col.f32.f16.f16.f32 "
        "{%0,%1,%2,%3}, {%4,%5,%6,%7}, {%8,%9}, {%0,%1,%2,%3};"
        : "+f"(c[0]), "+f"(c[1]), "+f"(c[2]), "+f"(c[3])
        : "r"(a[0]), "r"(a[1]), "r"(a[2]), "r"(a[3]), "r"(b[0]), "r"(b[1]));
}

__device__ __forceinline__ uint32_t hmul2u(uint32_t a, uint32_t b) {
    __half2 r = __hmul2(*reinterpret_cast<__half2*>(&a),
                        *reinterpret_cast<__half2*>(&b));
    return *reinterpret_cast<uint32_t*>(&r);
}

// -------- pre-kernel: feats fp32 -> fp16 --------
__global__ void __launch_bounds__(256) split_a_kernel(const float* __restrict__ x) {
    size_t i = ((size_t)blockIdx.x * blockDim.x + threadIdx.x) * 4;
    if (i < (size_t)M_TOTAL * 1024) {
        const size_t m = i >> 10;
        const size_t d = i & 1023;
        const float* p = x + m * LDX + d;   // stride 1025: no LDG.128 allowed
        *reinterpret_cast<__half2*>(g_A + i)     = __floats2half2_rn(p[0], p[1]);
        *reinterpret_cast<__half2*>(g_A + i + 2) = __floats2half2_rn(p[2], p[3]);
    }
}

// -------- pre-kernel: build P matrices (4 intervals x 3 powers) --------
__global__ void __launch_bounds__(256) build_p_kernel(const float* __restrict__ w) {
    const size_t idx = (size_t)blockIdx.x * 256 + threadIdx.x;  // d*1024+e
    if (idx >= (size_t)1 << 20) return;
    const float w0 = w[idx];
    const float w1 = w[(size_t)1 * 1048576 + idx];
    const float w2 = w[(size_t)2 * 1048576 + idx];
    const float w3 = w[(size_t)3 * 1048576 + idx];
    const float w4 = w[(size_t)4 * 1048576 + idx];
    const float w5 = w[(size_t)5 * 1048576 + idx];
    float p0 = w0, p1 = w1, p2 = w2;
    #pragma unroll
    for (int i = 0; i < 4; ++i) {
        const size_t base = (size_t)i * 3 * 1048576 + idx;
        g_P[base]               = __float2half_rn(p0);
        g_P[base + 1048576]     = __float2half_rn(p1);
        g_P[base + 2 * 1048576] = __float2half_rn(p2);
        if (i == 0) { p0 += 0.0625f * w3; p1 -= 0.5f * w3; p2 += w3; }
        if (i == 1) { p0 += 0.25f   * w4; p1 -= 1.0f * w4; p2 += w4; }
        if (i == 2) { p0 += 0.5625f * w5; p1 -= 1.5f * w5; p2 += w5; }
    }
}

// -------- bucket kernel: partition rows by interval (1 CTA, smem t-cache) ---
__global__ void __launch_bounds__(1024) bucket_kernel(const float* __restrict__ x) {
    extern __shared__ float t_cache[];          // 32768 floats = 128KB
    __shared__ int s_cnt[4], s_cur[4];
    const int tid = threadIdx.x;
    if (tid < 4) s_cnt[tid] = 0;
    for (int i = tid; i < PAD_M; i += 1024) g_perm[i] = -1;
    for (int i = tid; i < MAX_TILES; i += 1024) g_tile_int[i] = -1;

    // single gmem pass: strided t loads into smem cache
    for (int i = tid; i < M_TOTAL; i += 1024)
        t_cache[i] = x[(size_t)i * LDX + 1024];
    __syncthreads();

    const int base = tid * 32;
    int c[4] = {0, 0, 0, 0};
    #pragma unroll 4
    for (int r = 0; r < 32; ++r) {
        const float t = t_cache[base + r];
        c[(t > 0.25f) + (t > 0.5f) + (t > 0.75f)]++;
    }
    #pragma unroll
    for (int i = 0; i < 4; ++i) atomicAdd(&s_cnt[i], c[i]);
    __syncthreads();

    if (tid == 0) {
        int s = 0;
        #pragma unroll
        for (int i = 0; i < 4; ++i) {
            const int nt = (s_cnt[i] + 127) >> 7;
            const int ts = s >> 7;
            for (int j = 0; j < nt; ++j) g_tile_int[ts + j] = i;
            s_cur[i] = s;
            s += nt * 128;
        }
    }
    __syncthreads();

    int my[4];
    #pragma unroll
    for (int i = 0; i < 4; ++i) my[i] = atomicAdd(&s_cur[i], c[i]);
    for (int r = 0; r < 32; ++r) {
        const float t = t_cache[base + r];
        const int iv = (t > 0.25f) + (t > 0.5f) + (t > 0.75f);
        const int pos = my[iv]++;
        g_perm[pos] = base + r;
        g_tp[pos] = t;
    }
}

// -------- stage loader --------
__device__ __forceinline__ void load_stage(uint32_t sbase, int it,
                                           const int* __restrict__ perm_s,
                                           const __half* __restrict__ Pbase,
                                           int n0, int tid) {
    const int d0  = (it & (SEG_ITERS - 1)) * K_TILE;
    const int kg0 = it * K_TILE;
    const uint32_t sA = sbase;
    const uint32_t sB = sbase + 16384;
    #pragma unroll
    for (int r = 0; r < 4; ++r) {
        const int task = tid + r * 256;
        const int m = task >> 3;
        const int c = task & 7;
        const int rg = perm_s[m] < 0 ? 0 : perm_s[m];
        cp16(sA + swzA(m, c * 8), g_A + (size_t)rg * 1024 + d0 + c * 8);
    }
    #pragma unroll
    for (int r = 0; r < 4; ++r) {
        const int task = tid + r * 256;
        const int k = task >> 4;
        const int c = task & 15;
        cp16(sB + swzB(k, c * 8), Pbase + (size_t)(kg0 + k) * N_TOTAL + n0 + c * 8);
    }
}

// -------- main GEMM kernel: 2 CTAs/SM --------
__global__ void __launch_bounds__(THREADS, 2)
vclinear_gemm(const float* __restrict__ bias,
              float* __restrict__ out) {
    const int mt = blockIdx.x >> 3;
    const int interval = g_tile_int[mt];
    if (interval < 0) return;
    const int n0 = (blockIdx.x & 7) * N_TILE;

    extern __shared__ char smem[];
    const uint32_t sb = smem_u32(smem);
    const int tid = threadIdx.x;
    const int wid = tid >> 5;
    const int lane = tid & 31;
    const int warp_m = wid & 1;
    const int warp_n = wid >> 1;

    int* perm_s = reinterpret_cast<int*>(smem + SM_PERM);
    float* t_s  = reinterpret_cast<float*>(smem + SM_T);
    if (tid < M_TILE) {
        perm_s[tid] = g_perm[mt * M_TILE + tid];
        t_s[tid]    = g_tp[mt * M_TILE + tid];
    }
    __syncthreads();

    const __half* Pbase = g_P + (size_t)interval * K_RED * N_TOTAL;

    #pragma unroll
    for (int s = 0; s < STAGES - 1; ++s) {
        load_stage(sb + s * STAGE_BYTES, s, perm_s, Pbase, n0, tid);
        CP_COMMIT();
    }

    float acc[4][4][4];
    #pragma unroll
    for (int a = 0; a < 4; ++a)
        #pragma unroll
        for (int b = 0; b < 4; ++b)
            #pragma unroll
            for (int i = 0; i < 4; ++i) acc[a][b][i] = 0.0f;

    const int a_row   = warp_m * 64 + (lane & 15);
    const int a_khalf = (lane >> 4) * 8;
    const int b_krow  = (lane & 7) + (lane & 8);
    const int b_nhalf = (lane >> 4) * 8;
    const int t_row   = warp_m * 64 + (lane >> 2);   // fragment row (half 0)

    uint32_t bA0[4], bA1[4];   // half2 t^p broadcast (valid when p >= 1)

    int stage = 0;             // smem slot of current iteration
    for (int it = 0; it < ITERS; ++it) {
        if (it == SEG_ITERS || it == 2 * SEG_ITERS) {
            const bool sq = (it == 2 * SEG_ITERS);
            #pragma unroll
            for (int m = 0; m < 4; ++m) {
                float u0 = t_s[t_row + m * 16];
                float u1 = t_s[t_row + m * 16 + 8];
                if (sq) { u0 *= u0; u1 *= u1; }
                __half2 h0 = __float2half2_rn(u0);
                __half2 h1 = __float2half2_rn(u1);
                bA0[m] = *reinterpret_cast<uint32_t*>(&h0);
                bA1[m] = *reinterpret_cast<uint32_t*>(&h1);
            }
        }
        const bool scale = it >= SEG_ITERS;

        CP_WAIT(STAGES - 2);
        __syncthreads();   // single barrier per iteration: stage ready + prior reads done
        const uint32_t st  = sb + stage * STAGE_BYTES;
        const uint32_t stB = st + 16384;

        #pragma unroll
        for (int ks = 0; ks < 4; ++ks) {
            const int k0 = ks * 16;
            uint32_t ah[4][4], bh[4][2];
            #pragma unroll
            for (int m = 0; m < 4; ++m) {
                const uint32_t off = swzA(a_row + m * 16, k0 + a_khalf);
                LDSM_X4(ah[m][0], ah[m][1], ah[m][2], ah[m][3], st + off);
                if (scale) {
                    ah[m][0] = hmul2u(ah[m][0], bA0[m]);
                    ah[m][1] = hmul2u(ah[m][1], bA1[m]);
                    ah[m][2] = hmul2u(ah[m][2], bA0[m]);
                    ah[m][3] = hmul2u(ah[m][3], bA1[m]);
                }
            }
            #pragma unroll
            for (int bt = 0; bt < 2; ++bt) {
                const int n = warp_n * 32 + bt * 16 + b_nhalf;
                const uint32_t off = swzB(k0 + b_krow, n);
                LDSM_X4T(bh[2 * bt][0], bh[2 * bt][1],
                         bh[2 * bt + 1][0], bh[2 * bt + 1][1], stB + off);
            }
            #pragma unroll
            for (int m = 0; m < 4; ++m)
                #pragma unroll
                for (int n = 0; n < 4; ++n)
                    mma16816(acc[m][n], ah[m], bh[n]);
        }

        if (it + STAGES - 1 < ITERS) {
            // writes slot read at iter it-1; fenced by this iter's __syncthreads
            const int wslot = (stage + STAGES - 1 >= STAGES)
                                  ? stage - 1 : stage + STAGES - 1;
            load_stage(sb + wslot * STAGE_BYTES, it + STAGES - 1,
                       perm_s, Pbase, n0, tid);
        }
        CP_COMMIT();
        stage = (stage + 1 == STAGES) ? 0 : stage + 1;
    }

    // epilogue: scatter rows via perm, add bias
    #pragma unroll
    for (int m = 0; m < 4; ++m) {
        #pragma unroll
        for (int half = 0; half < 2; ++half) {
            const int rl = warp_m * 64 + m * 16 + (lane >> 2) + half * 8;
            const int rg = perm_s[rl];
            if (rg < 0) continue;
            float* orow = out + (size_t)rg * N_TOTAL;
            #pragma unroll
            for (int n = 0; n < 4; ++n) {
                const int col = n0 + warp_n * 32 + n * 8 + (lane & 3) * 2;
                float2 v;
                v.x = acc[m][n][half * 2 + 0] + __ldg(bias + col);
                v.y = acc[m][n][half * 2 + 1] + __ldg(bias + col + 1);
                *reinterpret_cast<float2*>(orow + col) = v;
            }
        }
    }
}

// -------- launch --------
extern "C" void kernel_launch(void* const* d_in, const int* in_sizes, int n_in,
                              void* d_out, int out_size) {
    const float* x    = (const float*)d_in[0];   // (32768, 1025)
    const float* w    = (const float*)d_in[1];   // (6,1024,1024)
    const float* bias = (const float*)d_in[2];   // (1024,)
    float* out = (float*)d_out;                  // (32768, 1024)

    static bool attr_set = false;
    if (!attr_set) {
        cudaFuncSetAttribute(vclinear_gemm,
                             cudaFuncAttributeMaxDynamicSharedMemorySize, SMEM_TOTAL);
        cudaFuncSetAttribute(bucket_kernel,
                             cudaFuncAttributeMaxDynamicSharedMemorySize,
                             M_TOTAL * (int)sizeof(float));
        attr_set = true;
    }

    split_a_kernel<<<(M_TOTAL * 1024 / 4 + 255) / 256, 256>>>(x);
    bucket_kernel<<<1, 1024, M_TOTAL * sizeof(float)>>>(x);
    build_p_kernel<<<(1 << 20) / 256, 256>>>(w);

    vclinear_gemm<<<MAX_TILES * 8, THREADS, SMEM_TOTAL>>>(bias, out);
}

// round 11
// speedup vs baseline: 5.1832x; 1.0658x over previous
#include <cuda_runtime.h>
#include <cuda_fp16.h>
#include <cstdint>

// ============================================================================
// VCLinear: out[b,e] = sum_c basis_c(t_b) * (feats @ W_c)[b,e] + bias[e]
//
// Spline identity: per knot interval I, out[b] = sum_p t^p (feats @ P_p^I) + b.
// R10: A-fragment reuse across the 3 powers. 32 d-chunks of K=32; per chunk
// load A once + 3 B tiles (one per power); per k16: 4 LDSM A reused for
// 3x(2 LDSM B + 16 MMA), progressive in-register t-scaling of A fragments.
// LDSM per 48 MMA: 18 -> 10; A gmem traffic /3; 32 barriers vs 48.
// ============================================================================

#define M_TOTAL   32768
#define N_TOTAL   1024
#define LDX       1025
#define PAD_M     33280
#define MAX_TILES 260

#define M_TILE    128
#define N_TILE    128
#define THREADS   256
#define D_CHUNKS  32                 // 1024 / 32
#define K_DC      32                 // K per d-chunk

// smem: A ring 3 x 8K | B ring 9 x 8K | perm | t
#define SM_B        24576
#define SM_PERM     98304
#define SM_T        98816
#define SMEM_TOTAL  99328

// -------- device scratch --------
__device__ __align__(16) __half g_A[(size_t)M_TOTAL * 1024];
__device__ __align__(16) __half g_P[(size_t)4 * 3072 * N_TOTAL];  // 25 MB
__device__ int   g_perm[PAD_M];
__device__ float g_tp[PAD_M];
__device__ int   g_tile_int[MAX_TILES];

// -------- helpers --------
__device__ __forceinline__ uint32_t smem_u32(const void* p) {
    uint32_t a;
    asm("{ .reg .u64 t; cvta.to.shared.u64 t, %1; cvt.u32.u64 %0, t; }"
        : "=r"(a) : "l"(p));
    return a;
}

// A tile 128 rows x 32 halfs (64B/row) packed as 64 double-rows of 128B.
// chunk = (m&1)*4 + k/8; chunk ^= (m>>1)&7 -> ldmatrix phases (8 consecutive
// rows, fixed k-octet) hit 8 distinct 16B groups: conflict-free.
__device__ __forceinline__ uint32_t swzA32(int m, int k) {
    const uint32_t chunk = (uint32_t)(((m & 1) << 2) | ((k >> 3) & 3));
    const uint32_t dr = (uint32_t)(m >> 1);
    return dr * 128 + ((chunk ^ (dr & 7)) << 4) + (uint32_t)(k & 7) * 2;
}
// B tile 32 k-rows x 128 n (256B/row): chunk' = chunk ^ (k&7)  (proven R7-R9).
__device__ __forceinline__ uint32_t swzB(int k, int n) {
    return (uint32_t)(k * 256 + ((((n >> 3) ^ (k & 7)) & 15) << 4) + (n & 7) * 2);
}

__device__ __forceinline__ void cp16(uint32_t dst, const void* src) {
    asm volatile("cp.async.cg.shared.global [%0], [%1], 16;"
                 :: "r"(dst), "l"(src) : "memory");
}

#define CP_COMMIT() asm volatile("cp.async.commit_group;" ::: "memory")
#define CP_WAIT(n)  asm volatile("cp.async.wait_group %0;" :: "n"(n) : "memory")

#define LDSM_X4(r0, r1, r2, r3, addr) \
    asm volatile("ldmatrix.sync.aligned.m8n8.x4.shared.b16 {%0,%1,%2,%3}, [%4];" \
                 : "=r"(r0), "=r"(r1), "=r"(r2), "=r"(r3) : "r"(addr))
#define LDSM_X4T(r0, r1, r2, r3, addr) \
    asm volatile("ldmatrix.sync.aligned.m8n8.x4.trans.shared.b16 {%0,%1,%2,%3}, [%4];" \
                 : "=r"(r0), "=r"(r1), "=r"(r2), "=r"(r3) : "r"(addr))

__device__ __forceinline__ void mma16816(float* c, const uint32_t* a, const uint32_t* b) {
    asm volatile(
        "mma.sync.aligned.m16n8k16.row.col.f32.f16.f16.f32 "
        "{%0,%1,%2,%3}, {%4,%5,%6,%7}, {%8,%9}, {%0,%1,%2,%3};"
        : "+f"(c[0]), "+f"(c[1]), "+f"(c[2]), "+f"(c[3])
        : "r"(a[0]), "r"(a[1]), "r"(a[2]), "r"(a[3]), "r"(b[0]), "r"(b[1]));
}

__device__ __forceinline__ uint32_t hmul2u(uint32_t a, uint32_t b) {
    __half2 r = __hmul2(*reinterpret_cast<__half2*>(&a),
                        *reinterpret_cast<__half2*>(&b));
    return *reinterpret_cast<uint32_t*>(&r);
}

// -------- pre-kernel: feats fp32 -> fp16 --------
__global__ void __launch_bounds__(256) split_a_kernel(const float* __restrict__ x) {
    size_t i = ((size_t)blockIdx.x * blockDim.x + threadIdx.x) * 4;
    if (i < (size_t)M_TOTAL * 1024) {
        const size_t m = i >> 10;
        const size_t d = i & 1023;
        const float* p = x + m * LDX + d;   // stride 1025: no LDG.128 allowed
        *reinterpret_cast<__half2*>(g_A + i)     = __floats2half2_rn(p[0], p[1]);
        *reinterpret_cast<__half2*>(g_A + i + 2) = __floats2half2_rn(p[2], p[3]);
    }
}

// -------- pre-kernel: build P (4 intervals x 3 powers) --------
__global__ void __launch_bounds__(256) build_p_kernel(const float* __restrict__ w) {
    const size_t idx = (size_t)blockIdx.x * 256 + threadIdx.x;  // d*1024+e
    if (idx >= (size_t)1 << 20) return;
    const float w0 = w[idx];
    const float w1 = w[(size_t)1 * 1048576 + idx];
    const float w2 = w[(size_t)2 * 1048576 + idx];
    const float w3 = w[(size_t)3 * 1048576 + idx];
    const float w4 = w[(size_t)4 * 1048576 + idx];
    const float w5 = w[(size_t)5 * 1048576 + idx];
    float p0 = w0, p1 = w1, p2 = w2;
    #pragma unroll
    for (int i = 0; i < 4; ++i) {
        const size_t base = (size_t)i * 3 * 1048576 + idx;
        g_P[base]               = __float2half_rn(p0);
        g_P[base + 1048576]     = __float2half_rn(p1);
        g_P[base + 2 * 1048576] = __float2half_rn(p2);
        if (i == 0) { p0 += 0.0625f * w3; p1 -= 0.5f * w3; p2 += w3; }
        if (i == 1) { p0 += 0.25f   * w4; p1 -= 1.0f * w4; p2 += w4; }
        if (i == 2) { p0 += 0.5625f * w5; p1 -= 1.5f * w5; p2 += w5; }
    }
}

// -------- bucket kernel (1 CTA, smem t-cache) --------
__global__ void __launch_bounds__(1024) bucket_kernel(const float* __restrict__ x) {
    extern __shared__ float t_cache[];
    __shared__ int s_cnt[4], s_cur[4];
    const int tid = threadIdx.x;
    if (tid < 4) s_cnt[tid] = 0;
    for (int i = tid; i < PAD_M; i += 1024) g_perm[i] = -1;
    for (int i = tid; i < MAX_TILES; i += 1024) g_tile_int[i] = -1;
    for (int i = tid; i < M_TOTAL; i += 1024)
        t_cache[i] = x[(size_t)i * LDX + 1024];
    __syncthreads();

    const int base = tid * 32;
    int c[4] = {0, 0, 0, 0};
    #pragma unroll 4
    for (int r = 0; r < 32; ++r) {
        const float t = t_cache[base + r];
        c[(t > 0.25f) + (t > 0.5f) + (t > 0.75f)]++;
    }
    #pragma unroll
    for (int i = 0; i < 4; ++i) atomicAdd(&s_cnt[i], c[i]);
    __syncthreads();

    if (tid == 0) {
        int s = 0;
        #pragma unroll
        for (int i = 0; i < 4; ++i) {
            const int nt = (s_cnt[i] + 127) >> 7;
            const int ts = s >> 7;
            for (int j = 0; j < nt; ++j) g_tile_int[ts + j] = i;
            s_cur[i] = s;
            s += nt * 128;
        }
    }
    __syncthreads();

    int my[4];
    #pragma unroll
    for (int i = 0; i < 4; ++i) my[i] = atomicAdd(&s_cur[i], c[i]);
    for (int r = 0; r < 32; ++r) {
        const float t = t_cache[base + r];
        const int iv = (t > 0.25f) + (t > 0.5f) + (t > 0.75f);
        const int pos = my[iv]++;
        g_perm[pos] = base + r;
        g_tp[pos] = t;
    }
}

// -------- per-d-chunk loader: A (8K) + 3 B tiles (24K) --------
__device__ __forceinline__ void load_chunk(uint32_t sb, int j,
                                           const int* __restrict__ perm_s,
                                           const __half* __restrict__ Pbase,
                                           int n0, int tid) {
    const int d0 = j * K_DC;
    const uint32_t aBase = sb + (uint32_t)(j % 3) * 8192;
    // A: 512 x 16B chunks (2 rounds)
    #pragma unroll
    for (int r = 0; r < 2; ++r) {
        const int task = tid + r * 256;
        const int m = task >> 2;
        const int kc = task & 3;
        const int rg = perm_s[m] < 0 ? 0 : perm_s[m];
        cp16(aBase + swzA32(m, kc * 8), g_A + (size_t)rg * 1024 + d0 + kc * 8);
    }
    // B: 3 powers x 512 chunks (2 rounds each)
    #pragma unroll
    for (int p = 0; p < 3; ++p) {
        const uint32_t bBase = sb + SM_B + (uint32_t)((j % 3) * 3 + p) * 8192;
        const __half* src = Pbase + (size_t)(p * 1024 + d0) * N_TOTAL + n0;
        #pragma unroll
        for (int r = 0; r < 2; ++r) {
            const int task = tid + r * 256;
            const int k = task >> 4;
            const int c = task & 15;
            cp16(bBase + swzB(k, c * 8), src + (size_t)k * N_TOTAL + c * 8);
        }
    }
}

// -------- main GEMM kernel: 2 CTAs/SM --------
__global__ void __launch_bounds__(THREADS, 2)
vclinear_gemm(const float* __restrict__ bias,
              float* __restrict__ out) {
    const int mt = blockIdx.x >> 3;
    const int interval = g_tile_int[mt];
    if (interval < 0) return;
    const int n0 = (blockIdx.x & 7) * N_TILE;

    extern __shared__ char smem[];
    const uint32_t sb = smem_u32(smem);
    const int tid = threadIdx.x;
    const int wid = tid >> 5;
    const int lane = tid & 31;
    const int warp_m = wid & 1;
    const int warp_n = wid >> 1;

    int* perm_s = reinterpret_cast<int*>(smem + SM_PERM);
    float* t_s  = reinterpret_cast<float*>(smem + SM_T);
    if (tid < M_TILE) {
        perm_s[tid] = g_perm[mt * M_TILE + tid];
        t_s[tid]    = g_tp[mt * M_TILE + tid];
    }
    __syncthreads();

    const __half* Pbase = g_P + (size_t)interval * 3072 * N_TOTAL;

    // prologue: chunks 0 and 1 in flight
    load_chunk(sb, 0, perm_s, Pbase, n0, tid);
    CP_COMMIT();
    load_chunk(sb, 1, perm_s, Pbase, n0, tid);
    CP_COMMIT();

    float acc[4][4][4];
    #pragma unroll
    for (int a = 0; a < 4; ++a)
        #pragma unroll
        for (int b = 0; b < 4; ++b)
            #pragma unroll
            for (int i = 0; i < 4; ++i) acc[a][b][i] = 0.0f;

    const int a_row   = warp_m * 64 + (lane & 15);
    const int a_koct  = (lane >> 4) * 8;
    const int b_krow  = (lane & 7) + (lane & 8);
    const int b_nhalf = (lane >> 4) * 8;
    const int t_row   = warp_m * 64 + (lane >> 2);

    // t broadcast (half2) for fragment rows r (bT0) and r+8 (bT1)
    uint32_t bT0[4], bT1[4];
    #pragma unroll
    for (int m = 0; m < 4; ++m) {
        __half2 h0 = __float2half2_rn(t_s[t_row + m * 16]);
        __half2 h1 = __float2half2_rn(t_s[t_row + m * 16 + 8]);
        bT0[m] = *reinterpret_cast<uint32_t*>(&h0);
        bT1[m] = *reinterpret_cast<uint32_t*>(&h1);
    }

    for (int j = 0; j < D_CHUNKS; ++j) {
        CP_WAIT(1);          // chunk j resident (chunk j+1 still in flight)
        __syncthreads();

        if (j + 2 < D_CHUNKS)
            load_chunk(sb, j + 2, perm_s, Pbase, n0, tid);
        CP_COMMIT();

        const uint32_t aBase  = sb + (uint32_t)(j % 3) * 8192;
        const uint32_t bBase0 = sb + SM_B + (uint32_t)((j % 3) * 3) * 8192;

        #pragma unroll
        for (int ks = 0; ks < 2; ++ks) {
            const int k0 = ks * 16;
            uint32_t ah[4][4];
            #pragma unroll
            for (int m = 0; m < 4; ++m) {
                const uint32_t off = swzA32(a_row + m * 16, k0 + a_koct);
                LDSM_X4(ah[m][0], ah[m][1], ah[m][2], ah[m][3], aBase + off);
            }
            #pragma unroll
            for (int p = 0; p < 3; ++p) {
                const uint32_t bBase = bBase0 + (uint32_t)p * 8192;
                uint32_t bh[4][2];
                #pragma unroll
                for (int bt = 0; bt < 2; ++bt) {
                    const int n = warp_n * 32 + bt * 16 + b_nhalf;
                    const uint32_t off = swzB(k0 + b_krow, n);
                    LDSM_X4T(bh[2 * bt][0], bh[2 * bt][1],
                             bh[2 * bt + 1][0], bh[2 * bt + 1][1], bBase + off);
                }
                #pragma unroll
                for (int m = 0; m < 4; ++m)
                    #pragma unroll
                    for (int n = 0; n < 4; ++n)
                        mma16816(acc[m][n], ah[m], bh[n]);
                if (p < 2) {
                    // progressive scale: ah *= t  (p1 sees t, p2 sees t^2)
                    #pragma unroll
                    for (int m = 0; m < 4; ++m) {
                        ah[m][0] = hmul2u(ah[m][0], bT0[m]);
                        ah[m][1] = hmul2u(ah[m][1], bT1[m]);
                        ah[m][2] = hmul2u(ah[m][2], bT0[m]);
                        ah[m][3] = hmul2u(ah[m][3], bT1[m]);
                    }
                }
            }
        }
    }

    // epilogue: scatter rows via perm, add bias
    #pragma unroll
    for (int m = 0; m < 4; ++m) {
        #pragma unroll
        for (int half = 0; half < 2; ++half) {
            const int rl = warp_m * 64 + m * 16 + (lane >> 2) + half * 8;
            const int rg = perm_s[rl];
            if (rg < 0) continue;
            float* orow = out + (size_t)rg * N_TOTAL;
            #pragma unroll
            for (int n = 0; n < 4; ++n) {
                const int col = n0 + warp_n * 32 + n * 8 + (lane & 3) * 2;
                float2 v;
                v.x = acc[m][n][half * 2 + 0] + __ldg(bias + col);
                v.y = acc[m][n][half * 2 + 1] + __ldg(bias + col + 1);
                *reinterpret_cast<float2*>(orow + col) = v;
            }
        }
    }
}

// -------- launch --------
extern "C" void kernel_launch(void* const* d_in, const int* in_sizes, int n_in,
                              void* d_out, int out_size) {
    const float* x    = (const float*)d_in[0];   // (32768, 1025)
    const float* w    = (const float*)d_in[1];   // (6,1024,1024)
    const float* bias = (const float*)d_in[2];   // (1024,)
    float* out = (float*)d_out;                  // (32768, 1024)

    static bool attr_set = false;
    if (!attr_set) {
        cudaFuncSetAttribute(vclinear_gemm,
                             cudaFuncAttributeMaxDynamicSharedMemorySize, SMEM_TOTAL);
        cudaFuncSetAttribute(bucket_kernel,
                             cudaFuncAttributeMaxDynamicSharedMemorySize,
                             M_TOTAL * (int)sizeof(float));
        attr_set = true;
    }

    split_a_kernel<<<(M_TOTAL * 1024 / 4 + 255) / 256, 256>>>(x);
    bucket_kernel<<<1, 1024, M_TOTAL * sizeof(float)>>>(x);
    build_p_kernel<<<(1 << 20) / 256, 256>>>(w);

    vclinear_gemm<<<MAX_TILES * 8, THREADS, SMEM_TOTAL>>>(bias, out);
}